// round 8
// baseline (speedup 1.0000x reference)
#include <cuda_runtime.h>
#include <cstdint>
#include <cstddef>

// Problem constants
#define L_S_C   4096
#define QSTART  2048
#define L_NS_C  64
#define LQ      2112
#define LK      4160
#define DM      1024
#define NH      16
#define DH      64

// Scratch (device globals). g_Q padded +64 rows for the clamped last q-block.
__device__ float g_Q[(size_t)(LQ + 64) * DM];
__device__ float g_K[(size_t)LK * DM];
__device__ float g_V[(size_t)LK * DM];
__device__ float g_AO[(size_t)LQ * DM];          // k-permuted layout
__device__ float g_xr[(size_t)LK * DM];          // rounded x, k-permuted
__device__ float g_Wsr[(size_t)(3 * DM) * DM];   // rounded W_S^T [n][k], k-permuted
__device__ float g_Wor[(size_t)DM * DM];         // rounded W_out^T [n][k], k-permuted
__device__ float g_Kp[(size_t)LK * DM];          // K, head-dim 8-block permuted
__device__ float g_Vt[(size_t)DM * LK];          // V^T [d][token], token 8-block permuted

// 8-block permutation: stored position p holds orig col sigma(p):
// sigma(2t)=t, sigma(2t+1)=t+4  -> stored order [0,4,1,5,2,6,3,7].
// Inverse: pos(c) = c<4 ? 2c : 2c-7.

__device__ __forceinline__ uint32_t f2tf(float x) {
    uint32_t r;
    asm("cvt.rna.tf32.f32 %0, %1;" : "=r"(r) : "f"(x));
    return r;
}
__device__ __forceinline__ float rnd(float x) { return __uint_as_float(f2tf(x)); }
__device__ __forceinline__ uint32_t fu(float x) { return __float_as_uint(x); }

__device__ __forceinline__ void mma8(float* c, const uint32_t* a, const uint32_t* b) {
    asm volatile(
        "mma.sync.aligned.m16n8k8.row.col.f32.tf32.tf32.f32 "
        "{%0,%1,%2,%3}, {%4,%5,%6,%7}, {%8,%9}, {%0,%1,%2,%3};\n"
        : "+f"(c[0]), "+f"(c[1]), "+f"(c[2]), "+f"(c[3])
        : "r"(a[0]), "r"(a[1]), "r"(a[2]), "r"(a[3]), "r"(b[0]), "r"(b[1]));
}

__device__ __forceinline__ void cp16(void* dst, const void* src, int sz) {
    uint32_t d = (uint32_t)__cvta_generic_to_shared(dst);
    asm volatile("cp.async.cg.shared.global [%0], [%1], 16, %2;\n"
                 :: "r"(d), "l"(src), "r"(sz));
}
#define CP_COMMIT()  asm volatile("cp.async.commit_group;\n")
#define CP_WAIT(n)   asm volatile("cp.async.wait_group %0;\n" :: "n"(n))

// ============================================================================
// Prep: round+permute x; transpose+round+permute W_S / W_out.
// ============================================================================
__global__ void __launch_bounds__(256)
prep_x(const float* __restrict__ x) {
    const int NT8 = (int)((size_t)LK * DM / 8);
    for (int i = blockIdx.x * blockDim.x + threadIdx.x; i < NT8;
         i += gridDim.x * blockDim.x) {
        const float4* s = (const float4*)x + 2 * i;
        float4 v0 = s[0], v1 = s[1];
        float4 w0 = make_float4(rnd(v0.x), rnd(v1.x), rnd(v0.y), rnd(v1.y));
        float4 w1 = make_float4(rnd(v0.z), rnd(v1.z), rnd(v0.w), rnd(v1.w));
        ((float4*)g_xr)[2 * i]     = w0;
        ((float4*)g_xr)[2 * i + 1] = w1;
    }
}

__global__ void __launch_bounds__(256)
prep_tr(const float* __restrict__ src, int which) {
    __shared__ float t[32][33];
    const int C = which ? DM : 3 * DM;
    float* dst = which ? g_Wor : g_Wsr;
    const int c0 = blockIdx.x * 32, r0 = blockIdx.y * 32;
    const int tx = threadIdx.x & 31, ty = threadIdx.x >> 5;
#pragma unroll
    for (int i = 0; i < 4; i++)
        t[ty + i * 8][tx] = rnd(src[(size_t)(r0 + ty + i * 8) * C + c0 + tx]);
    __syncthreads();
    const int tx8 = tx & 7;
    const int pk = (tx & ~7) + (tx8 < 4 ? 2 * tx8 : 2 * tx8 - 7);
#pragma unroll
    for (int i = 0; i < 4; i++)
        dst[(size_t)(c0 + ty + i * 8) * DM + r0 + pk] = t[tx][ty + i * 8];
}

// ============================================================================
// Repack for attention: K with head-dim 8-block permutation; V transposed
// [d][token] with token 8-block permutation.
// ============================================================================
__global__ void __launch_bounds__(256)
repack_K() {
    const int NT8 = (int)((size_t)LK * DM / 8);
    for (int i = blockIdx.x * blockDim.x + threadIdx.x; i < NT8;
         i += gridDim.x * blockDim.x) {
        const float4* s = (const float4*)g_K + 2 * i;
        float4 v0 = s[0], v1 = s[1];
        ((float4*)g_Kp)[2 * i]     = make_float4(v0.x, v1.x, v0.y, v1.y);
        ((float4*)g_Kp)[2 * i + 1] = make_float4(v0.z, v1.z, v0.w, v1.w);
    }
}

__global__ void __launch_bounds__(256)
repack_Vt() {
    __shared__ float t[32][33];
    const int tok0 = blockIdx.x * 32, d0 = blockIdx.y * 32;
    const int tx = threadIdx.x & 31, ty = threadIdx.x >> 5;
#pragma unroll
    for (int i = 0; i < 4; i++)
        t[ty + i * 8][tx] = g_V[(size_t)(tok0 + ty + i * 8) * DM + d0 + tx];
    __syncthreads();
    const int tx8 = tx & 7;
    const int ptok = (tx & ~7) + (tx8 < 4 ? 2 * tx8 : 2 * tx8 - 7);
#pragma unroll
    for (int i = 0; i < 4; i++)
        g_Vt[(size_t)(d0 + ty + i * 8) * LK + tok0 + ptok] = t[tx][ty + i * 8];
}

// ============================================================================
// tf32 warp-MMA GEMM tile (k-permuted operands -> LDS.64 fragments).
// 128x128x32 tiles, 256 thr, 8 warps each 64x32. Smem stride 40 (conflict-free
// LDS.64). Buffers: As0 @0, As1 @5120, Bs0 @10240, Bs1 @15360 (floats).
// MODE 0: scatter rnd() into g_Q/g_K/g_V (unpermuted). MODE 1: store into C.
// ============================================================================
template <int MODE>
__device__ __forceinline__ void gemm_tile(const float* __restrict__ A,
                                          const float* __restrict__ Bt,
                                          float* __restrict__ C,
                                          int M, int N, int K,
                                          int mBase, int nBase, float* sm) {
    float* As0 = sm;
    float* As1 = sm + 5120;
    float* Bs0 = sm + 10240;
    float* Bs1 = sm + 15360;

    const int tid  = threadIdx.x;
    const int warp = tid >> 5, lane = tid & 31;
    const int gid  = lane >> 2, tig = lane & 3;
    const int wm = (warp >> 2) * 64;
    const int wn = (warp & 3) * 32;

    const int ar = tid >> 3;
    const int ac = (tid & 7) << 2;

    float c[4][4][4];
#pragma unroll
    for (int i = 0; i < 4; i++)
#pragma unroll
        for (int j = 0; j < 4; j++)
#pragma unroll
            for (int e = 0; e < 4; e++) c[i][j][e] = 0.f;

    auto issue = [&](int k0, float* Asb, float* Bsb) {
#pragma unroll
        for (int i = 0; i < 4; i++) {
            int row = ar + i * 32;
            int grow = mBase + row;
            int ok = (MODE == 1) ? (grow < M) : 1;
            const float* asrc = A + (size_t)(ok ? grow : 0) * K + k0 + ac;
            cp16(&Asb[row * 40 + ac], asrc, ok ? 16 : 0);
            const float* bsrc = Bt + (size_t)(nBase + row) * K + k0 + ac;
            cp16(&Bsb[row * 40 + ac], bsrc, 16);
        }
        CP_COMMIT();
    };

    issue(0, As0, Bs0);

    const int T = K / 32;
    for (int t = 0; t < T; t++) {
        float* Asb = (t & 1) ? As1 : As0;
        float* Bsb = (t & 1) ? Bs1 : Bs0;
        if (t + 1 < T) {
            issue((t + 1) * 32, (t & 1) ? As0 : As1, (t & 1) ? Bs0 : Bs1);
            CP_WAIT(1);
        } else {
            CP_WAIT(0);
        }
        __syncthreads();

#pragma unroll
        for (int ks = 0; ks < 4; ks++) {
            const int kcol = ks * 8 + 2 * tig;   // stored pos pair -> cols (k, k+4)
            uint32_t a[4][4];
#pragma unroll
            for (int mt = 0; mt < 4; mt++) {
                int r = wm + mt * 16 + gid;
                float2 u = *(const float2*)&Asb[r * 40 + kcol];
                float2 w = *(const float2*)&Asb[(r + 8) * 40 + kcol];
                a[mt][0] = fu(u.x); a[mt][2] = fu(u.y);
                a[mt][1] = fu(w.x); a[mt][3] = fu(w.y);
            }
            uint32_t b[4][2];
#pragma unroll
            for (int nt = 0; nt < 4; nt++) {
                int rn = wn + nt * 8 + gid;
                float2 v = *(const float2*)&Bsb[rn * 40 + kcol];
                b[nt][0] = fu(v.x); b[nt][1] = fu(v.y);
            }
#pragma unroll
            for (int mt = 0; mt < 4; mt++)
#pragma unroll
                for (int nt = 0; nt < 4; nt++)
                    mma8(c[mt][nt], a[mt], b[nt]);
        }
        __syncthreads();
    }

#pragma unroll
    for (int mt = 0; mt < 4; mt++) {
#pragma unroll
        for (int nt = 0; nt < 4; nt++) {
#pragma unroll
            for (int e = 0; e < 4; e++) {
                int row = mBase + wm + mt * 16 + gid + ((e >> 1) << 3);
                int col = nBase + wn + nt * 8 + 2 * tig + (e & 1);
                float v = c[mt][nt][e];
                if (MODE == 0) {
                    v = rnd(v);
                    if (col < DM) {
                        if (row >= QSTART) g_Q[(size_t)(row - QSTART) * DM + col] = v;
                    } else if (col < 2 * DM) {
                        g_K[(size_t)row * DM + (col - DM)] = v;
                    } else {
                        g_V[(size_t)row * DM + (col - 2 * DM)] = v;
                    }
                } else {
                    if (row < M) C[(size_t)row * N + col] = v;
                }
            }
        }
    }
}

// ============================================================================
// Fused qkv: 640 live GEMM tiles + 192 NS streaming blocks (10:3 interleave).
// ============================================================================
__global__ void __launch_bounds__(256, 2)
fused_qkv(const float* __restrict__ x, const float* __restrict__ W_NS) {
    extern __shared__ float sm[];
    const int bid = blockIdx.x;
    const int grp = bid / 13, rem = bid % 13;
    if (rem < 10) {
        const int g = grp * 10 + rem;       // 0..639
        int mt, nt;
        if (g < 384) { mt = 16 + g / 24; nt = g % 24; }            // rows>=2048: QKV
        else { int g2 = g - 384; mt = g2 / 16; nt = 8 + g2 % 16; } // rows<2048: KV only
        gemm_tile<0>((const float*)g_xr, (const float*)g_Wsr, nullptr,
                     4096, 3072, 1024, mt * 128, nt * 128, sm);
    } else {
        const int ns  = grp * 3 + (rem - 10);   // 0..191
        const int tok = ns / 3;
        const int cb  = ns % 3;                 // 0=Q, 1=K, 2=V
        const int c4  = cb * 1024 + threadIdx.x * 4;

        const float* xr = x + (size_t)(L_S_C + tok) * DM;
        for (int i = threadIdx.x; i < DM; i += 256) sm[i] = xr[i];
        __syncthreads();

        const float* Wp = W_NS + (size_t)tok * DM * 3072 + c4;
        float4 acc = make_float4(0.f, 0.f, 0.f, 0.f);
#pragma unroll 8
        for (int d = 0; d < DM; d++) {
            float4 w = __ldcs((const float4*)(Wp + (size_t)d * 3072));
            float xv = sm[d];
            acc.x = fmaf(xv, w.x, acc.x);
            acc.y = fmaf(xv, w.y, acc.y);
            acc.z = fmaf(xv, w.z, acc.z);
            acc.w = fmaf(xv, w.w, acc.w);
        }
        acc.x = rnd(acc.x); acc.y = rnd(acc.y); acc.z = rnd(acc.z); acc.w = rnd(acc.w);

        float* dst;
        if (cb == 0)      dst = g_Q + (size_t)(QSTART + tok) * DM;
        else if (cb == 1) dst = g_K + (size_t)(L_S_C + tok) * DM;
        else              dst = g_V + (size_t)(L_S_C + tok) * DM;
        *(float4*)(dst + (c4 - cb * 1024)) = acc;
    }
}

__global__ void __launch_bounds__(256, 2)
gemm_out(float* __restrict__ C) {
    extern __shared__ float sm[];
    gemm_tile<1>((const float*)g_AO, (const float*)g_Wor, C, LQ, 1024, 1024,
                 blockIdx.y * 128, blockIdx.x * 128, sm);
}

// ============================================================================
// Flash attention v3: 128 q-rows per CTA, 256 thr / 8 warps. Q fragments in
// registers; K / V^T repacked with 8-block permutation -> all fragment loads
// are LDS.64. Smem = Ps[128][72] + 4 KV bufs [64][72] = 110.6 KB -> 2 CTA/SM.
// ============================================================================
__global__ void __launch_bounds__(256, 2)
attn_kernel() {
    extern __shared__ float sm[];
    float* Ps  = sm;              // [128][72] (Q staging, then P)
    float* KsA = sm + 9216;       // [64][72]
    float* KsB = sm + 13824;
    float* VsA = sm + 18432;
    float* VsB = sm + 23040;

    const int qtp = 16 - ((int)blockIdx.x >> 4);   // descending work size
    const int h   = blockIdx.x & 15;
    const int qb  = qtp * 128;
    const int tid  = threadIdx.x;
    const int warp = tid >> 5, lane = tid & 31;
    const int gid  = lane >> 2, tig = lane & 3;
    const int rq0  = warp * 16 + gid;

    auto loadKV = [&](int kt, float* Kd, float* Vd) {
        const float* kp = g_Kp + (size_t)kt * 64 * DM + h * DH;
        const float* vp = g_Vt + (size_t)h * DH * LK + kt * 64;
#pragma unroll
        for (int i = 0; i < 4; i++) {
            int idx = tid + i * 256;
            int r = idx >> 4, c4 = (idx & 15) << 2;
            cp16(&Kd[r * 72 + c4], kp + (size_t)r * DM + c4, 16);
            cp16(&Vd[r * 72 + c4], vp + (size_t)r * LK + c4, 16);
        }
        CP_COMMIT();
    };

    loadKV(0, KsA, VsA);

    // Stage Q (unpermuted) into Ps, extract register fragments, then free Ps.
    for (int i = tid; i < 128 * 16; i += 256) {
        int r = i >> 4, c4 = (i & 15) << 2;
        *(float4*)&Ps[r * 72 + c4] =
            *(const float4*)(g_Q + (size_t)(qb + r) * DM + h * DH + c4);
    }
    __syncthreads();
    uint32_t qa[8][4];
#pragma unroll
    for (int ks = 0; ks < 8; ks++) {
        qa[ks][0] = fu(Ps[rq0 * 72 + ks * 8 + tig] * 0.125f);
        qa[ks][2] = fu(Ps[rq0 * 72 + ks * 8 + tig + 4] * 0.125f);
        qa[ks][1] = fu(Ps[(rq0 + 8) * 72 + ks * 8 + tig] * 0.125f);
        qa[ks][3] = fu(Ps[(rq0 + 8) * 72 + ks * 8 + tig + 4] * 0.125f);
    }
    __syncthreads();

    const int p0 = (tig < 2) ? 4 * tig     : 4 * tig - 7;   // pos of col 2tig
    const int p1 = (tig < 2) ? 4 * tig + 2 : 4 * tig - 5;   // pos of col 2tig+1

    float m0 = -1e30f, m1 = -1e30f, l0 = 0.f, l1 = 0.f;
    float o[8][4];
#pragma unroll
    for (int i = 0; i < 8; i++)
#pragma unroll
        for (int e = 0; e < 4; e++) o[i][e] = 0.f;

    const int nktFull = 34 + 2 * qtp;
    const int nkt = nktFull < 65 ? nktFull : 65;
    for (int kt = 0; kt < nkt; kt++) {
        float* Ks = (kt & 1) ? KsB : KsA;
        float* Vs = (kt & 1) ? VsB : VsA;
        if (kt + 1 < nkt) {
            loadKV(kt + 1, (kt & 1) ? KsA : KsB, (kt & 1) ? VsA : VsB);
            CP_WAIT(1);
        } else {
            CP_WAIT(0);
        }
        __syncthreads();

        // S = Q @ K^T  (Q frags in regs, K frags LDS.64)
        float s[8][4];
#pragma unroll
        for (int i = 0; i < 8; i++)
#pragma unroll
            for (int e = 0; e < 4; e++) s[i][e] = 0.f;

#pragma unroll
        for (int ks = 0; ks < 8; ks++) {
            const int kcol = ks * 8 + 2 * tig;
#pragma unroll
            for (int nt = 0; nt < 8; nt++) {
                float2 bv = *(const float2*)&Ks[(nt * 8 + gid) * 72 + kcol];
                uint32_t bb[2] = {fu(bv.x), fu(bv.y)};
                mma8(s[nt], qa[ks], bb);
            }
        }

        // Causal mask on last two k-tiles
        if (kt >= nkt - 2) {
            const int off = kt * 64 - QSTART - qb;
#pragma unroll
            for (int nt = 0; nt < 8; nt++) {
#pragma unroll
                for (int e = 0; e < 4; e++) {
                    int kc  = nt * 8 + 2 * tig + (e & 1);
                    int rit = warp * 16 + gid + ((e >> 1) << 3);
                    if (kc + off > rit) s[nt][e] = -1e30f;
                }
            }
        }

        // Online softmax
        float rm0 = -1e30f, rm1 = -1e30f;
#pragma unroll
        for (int nt = 0; nt < 8; nt++) {
            rm0 = fmaxf(rm0, fmaxf(s[nt][0], s[nt][1]));
            rm1 = fmaxf(rm1, fmaxf(s[nt][2], s[nt][3]));
        }
        rm0 = fmaxf(rm0, __shfl_xor_sync(0xffffffffu, rm0, 1));
        rm0 = fmaxf(rm0, __shfl_xor_sync(0xffffffffu, rm0, 2));
        rm1 = fmaxf(rm1, __shfl_xor_sync(0xffffffffu, rm1, 1));
        rm1 = fmaxf(rm1, __shfl_xor_sync(0xffffffffu, rm1, 2));

        float mn0 = fmaxf(m0, rm0), mn1 = fmaxf(m1, rm1);
        float sc0 = __expf(m0 - mn0), sc1 = __expf(m1 - mn1);
        m0 = mn0; m1 = mn1;

        float rs0 = 0.f, rs1 = 0.f;
#pragma unroll
        for (int nt = 0; nt < 8; nt++) {
            s[nt][0] = __expf(s[nt][0] - m0); rs0 += s[nt][0];
            s[nt][1] = __expf(s[nt][1] - m0); rs0 += s[nt][1];
            s[nt][2] = __expf(s[nt][2] - m1); rs1 += s[nt][2];
            s[nt][3] = __expf(s[nt][3] - m1); rs1 += s[nt][3];
        }
        rs0 += __shfl_xor_sync(0xffffffffu, rs0, 1);
        rs0 += __shfl_xor_sync(0xffffffffu, rs0, 2);
        rs1 += __shfl_xor_sync(0xffffffffu, rs1, 1);
        rs1 += __shfl_xor_sync(0xffffffffu, rs1, 2);
        l0 = l0 * sc0 + rs0;
        l1 = l1 * sc1 + rs1;

#pragma unroll
        for (int dt = 0; dt < 8; dt++) {
            o[dt][0] *= sc0; o[dt][1] *= sc0;
            o[dt][2] *= sc1; o[dt][3] *= sc1;
        }

        // P -> Ps at permuted positions (warp-private rows), rounded tf32
#pragma unroll
        for (int nt = 0; nt < 8; nt++) {
            Ps[rq0 * 72 + nt * 8 + p0]       = rnd(s[nt][0]);
            Ps[rq0 * 72 + nt * 8 + p1]       = rnd(s[nt][1]);
            Ps[(rq0 + 8) * 72 + nt * 8 + p0] = rnd(s[nt][2]);
            Ps[(rq0 + 8) * 72 + nt * 8 + p1] = rnd(s[nt][3]);
        }
        __syncwarp();

        // O += P @ V   (P frags LDS.64, V^T frags LDS.64)
#pragma unroll
        for (int ks = 0; ks < 8; ks++) {
            const int kcol = ks * 8 + 2 * tig;
            float2 u = *(const float2*)&Ps[rq0 * 72 + kcol];
            float2 w = *(const float2*)&Ps[(rq0 + 8) * 72 + kcol];
            uint32_t a[4] = {fu(u.x), fu(w.x), fu(u.y), fu(w.y)};
#pragma unroll
            for (int dt = 0; dt < 8; dt++) {
                float2 bv = *(const float2*)&Vs[(dt * 8 + gid) * 72 + kcol];
                uint32_t bb[2] = {fu(bv.x), fu(bv.y)};
                mma8(o[dt], a, bb);
            }
        }
        __syncthreads();
    }

    // Epilogue: write g_AO in k-permuted layout (matches g_Wor for gemm_out)
    const float il0 = 1.f / l0, il1 = 1.f / l1;
    const int qr0 = qb + rq0, qr1 = qb + rq0 + 8;
#pragma unroll
    for (int dt = 0; dt < 8; dt++) {
        int base = h * DH + dt * 8;
        if (qr0 < LQ) {
            g_AO[(size_t)qr0 * DM + base + p0] = rnd(o[dt][0] * il0);
            g_AO[(size_t)qr0 * DM + base + p1] = rnd(o[dt][1] * il0);
        }
        if (qr1 < LQ) {
            g_AO[(size_t)qr1 * DM + base + p0] = rnd(o[dt][2] * il1);
            g_AO[(size_t)qr1 * DM + base + p1] = rnd(o[dt][3] * il1);
        }
    }
}

// ============================================================================
extern "C" void kernel_launch(void* const* d_in, const int* in_sizes, int n_in,
                              void* d_out, int out_size) {
    const float* x     = (const float*)d_in[0];
    const float* W_S   = (const float*)d_in[1];
    const float* W_NS  = (const float*)d_in[2];
    const float* W_out = (const float*)d_in[3];
    float* out = (float*)d_out;
    (void)in_sizes; (void)n_in; (void)out_size;

    const int gemm_smem = 4 * 5120 * (int)sizeof(float);   // 81920
    const int attn_smem = 27648 * (int)sizeof(float);      // 110592

    cudaFuncSetAttribute(fused_qkv,   cudaFuncAttributeMaxDynamicSharedMemorySize, gemm_smem);
    cudaFuncSetAttribute(gemm_out,    cudaFuncAttributeMaxDynamicSharedMemorySize, gemm_smem);
    cudaFuncSetAttribute(attn_kernel, cudaFuncAttributeMaxDynamicSharedMemorySize, attn_smem);

    // 0) prep: round+permute x; transpose+round+permute W_S, W_out
    prep_x<<<512, 256>>>(x);
    prep_tr<<<dim3(3 * DM / 32, DM / 32), 256>>>(W_S, 0);
    prep_tr<<<dim3(DM / 32, DM / 32), 256>>>(W_out, 1);

    // 1+2) fused: live qkv GEMM tiles (640) + NS streaming (192)
    fused_qkv<<<832, 256, gemm_smem>>>(x, W_NS);

    // 2b) repack K (col-permute) and V (transpose + token-permute)
    repack_K<<<1024, 256>>>();
    repack_Vt<<<dim3(LK / 32, DM / 32), 256>>>();

    // 3) attention: 17 q-pair tiles x 16 heads, longest first
    attn_kernel<<<17 * NH, 256, attn_smem>>>();

    // 4) output projection
    gemm_out<<<dim3(1024 / 128, (LQ + 127) / 128), 256, gemm_smem>>>(out);
}

// round 9
// speedup vs baseline: 1.0213x; 1.0213x over previous
#include <cuda_runtime.h>
#include <cstdint>
#include <cstddef>

// Problem constants
#define L_S_C   4096
#define QSTART  2048
#define L_NS_C  64
#define LQ      2112
#define LK      4160
#define DM      1024
#define NH      16
#define DH      64

// Scratch (device globals). g_Q padded +64 rows for the clamped last q-block.
__device__ float g_Q[(size_t)(LQ + 64) * DM];
__device__ float g_V[(size_t)LK * DM];
__device__ float g_AO[(size_t)LQ * DM];          // k-permuted layout
__device__ float g_xr[(size_t)LK * DM];          // rounded x (row-major [m][k]), k-permuted
__device__ float g_Wsr[(size_t)(3 * DM) * DM];   // rounded W_S^T [n][k], k-permuted
__device__ float g_Wor[(size_t)DM * DM];         // rounded W_out^T [n][k], k-permuted
__device__ float g_Kp[(size_t)LK * DM];          // K, head-dim 8-block permuted
__device__ float g_Vt[(size_t)DM * LK];          // V^T [d][token], token 8-block permuted

// 8-block permutation: stored position p holds orig col sigma(p):
// sigma(2t)=t, sigma(2t+1)=t+4  -> stored order [0,4,1,5,2,6,3,7].
// Inverse: pos(c) = c<4 ? 2c : 2c-7.

__device__ __forceinline__ uint32_t f2tf(float x) {
    uint32_t r;
    asm("cvt.rna.tf32.f32 %0, %1;" : "=r"(r) : "f"(x));
    return r;
}
__device__ __forceinline__ float rnd(float x) { return __uint_as_float(f2tf(x)); }
__device__ __forceinline__ uint32_t fu(float x) { return __float_as_uint(x); }

__device__ __forceinline__ void mma8(float* c, const uint32_t* a, const uint32_t* b) {
    asm volatile(
        "mma.sync.aligned.m16n8k8.row.col.f32.tf32.tf32.f32 "
        "{%0,%1,%2,%3}, {%4,%5,%6,%7}, {%8,%9}, {%0,%1,%2,%3};\n"
        : "+f"(c[0]), "+f"(c[1]), "+f"(c[2]), "+f"(c[3])
        : "r"(a[0]), "r"(a[1]), "r"(a[2]), "r"(a[3]), "r"(b[0]), "r"(b[1]));
}

__device__ __forceinline__ void cp16(void* dst, const void* src, int sz) {
    uint32_t d = (uint32_t)__cvta_generic_to_shared(dst);
    asm volatile("cp.async.cg.shared.global [%0], [%1], 16, %2;\n"
                 :: "r"(d), "l"(src), "r"(sz));
}
#define CP_COMMIT()  asm volatile("cp.async.commit_group;\n")
#define CP_WAIT(n)   asm volatile("cp.async.wait_group %0;\n" :: "n"(n))

// ============================================================================
// Prep: round+permute x; transpose+round+permute W_S / W_out.
// ============================================================================
__global__ void __launch_bounds__(256)
prep_x(const float* __restrict__ x) {
    const int NT8 = (int)((size_t)LK * DM / 8);
    for (int i = blockIdx.x * blockDim.x + threadIdx.x; i < NT8;
         i += gridDim.x * blockDim.x) {
        const float4* s = (const float4*)x + 2 * i;
        float4 v0 = s[0], v1 = s[1];
        float4 w0 = make_float4(rnd(v0.x), rnd(v1.x), rnd(v0.y), rnd(v1.y));
        float4 w1 = make_float4(rnd(v0.z), rnd(v1.z), rnd(v0.w), rnd(v1.w));
        ((float4*)g_xr)[2 * i]     = w0;
        ((float4*)g_xr)[2 * i + 1] = w1;
    }
}

__global__ void __launch_bounds__(256)
prep_tr(const float* __restrict__ src, int which) {
    __shared__ float t[32][33];
    const int C = which ? DM : 3 * DM;
    float* dst = which ? g_Wor : g_Wsr;
    const int c0 = blockIdx.x * 32, r0 = blockIdx.y * 32;
    const int tx = threadIdx.x & 31, ty = threadIdx.x >> 5;
#pragma unroll
    for (int i = 0; i < 4; i++)
        t[ty + i * 8][tx] = rnd(src[(size_t)(r0 + ty + i * 8) * C + c0 + tx]);
    __syncthreads();
    const int tx8 = tx & 7;
    const int pk = (tx & ~7) + (tx8 < 4 ? 2 * tx8 : 2 * tx8 - 7);
#pragma unroll
    for (int i = 0; i < 4; i++)
        dst[(size_t)(c0 + ty + i * 8) * DM + r0 + pk] = t[tx][ty + i * 8];
}

// V transpose repack: [d][token], token 8-block permuted.
__global__ void __launch_bounds__(256)
repack_Vt() {
    __shared__ float t[32][33];
    const int tok0 = blockIdx.x * 32, d0 = blockIdx.y * 32;
    const int tx = threadIdx.x & 31, ty = threadIdx.x >> 5;
#pragma unroll
    for (int i = 0; i < 4; i++)
        t[ty + i * 8][tx] = g_V[(size_t)(tok0 + ty + i * 8) * DM + d0 + tx];
    __syncthreads();
    const int tx8 = tx & 7;
    const int ptok = (tx & ~7) + (tx8 < 4 ? 2 * tx8 : 2 * tx8 - 7);
#pragma unroll
    for (int i = 0; i < 4; i++)
        g_Vt[(size_t)(d0 + ty + i * 8) * LK + tok0 + ptok] = t[tx][ty + i * 8];
}

// Zero d_out for atomic-accumulating split-K output projection.
__global__ void __launch_bounds__(256)
zeroC(float* __restrict__ C) {
    int i = blockIdx.x * blockDim.x + threadIdx.x;
    if (i < LQ * DM / 4) ((float4*)C)[i] = make_float4(0.f, 0.f, 0.f, 0.f);
}

// ============================================================================
// tf32 warp-MMA GEMM tile (k-permuted operands -> LDS.64 fragments).
// Single barrier per k-iter: CP_WAIT(all) -> barrier -> issue(t+1) -> compute.
// Buffers: As0 @0, As1 @5120, Bs0 @10240, Bs1 @15360 (floats, stride 40).
// MODE 0: scatter rnd() into g_Q/g_Kp(permuted)/g_V. MODE 1: atomicAdd into C.
// ============================================================================
template <int MODE>
__device__ __forceinline__ void gemm_tile(const float* __restrict__ A,
                                          const float* __restrict__ Bt,
                                          float* __restrict__ C,
                                          int M, int N, int Ks, int kBeg, int kLen,
                                          int mBase, int nBase, float* sm) {
    float* As0 = sm;
    float* As1 = sm + 5120;
    float* Bs0 = sm + 10240;
    float* Bs1 = sm + 15360;

    const int tid  = threadIdx.x;
    const int warp = tid >> 5, lane = tid & 31;
    const int gid  = lane >> 2, tig = lane & 3;
    const int wm = (warp >> 2) * 64;
    const int wn = (warp & 3) * 32;

    const int ar = tid >> 3;
    const int ac = (tid & 7) << 2;

    float c[4][4][4];
#pragma unroll
    for (int i = 0; i < 4; i++)
#pragma unroll
        for (int j = 0; j < 4; j++)
#pragma unroll
            for (int e = 0; e < 4; e++) c[i][j][e] = 0.f;

    auto issue = [&](int k0, float* Asb, float* Bsb) {
#pragma unroll
        for (int i = 0; i < 4; i++) {
            int row = ar + i * 32;
            int grow = mBase + row;
            int ok = (MODE == 1) ? (grow < M) : 1;
            const float* asrc = A + (size_t)(ok ? grow : 0) * Ks + k0 + ac;
            cp16(&Asb[row * 40 + ac], asrc, ok ? 16 : 0);
            const float* bsrc = Bt + (size_t)(nBase + row) * Ks + k0 + ac;
            cp16(&Bsb[row * 40 + ac], bsrc, 16);
        }
        CP_COMMIT();
    };

    issue(kBeg, As0, Bs0);

    const int T = kLen / 32;
    for (int t = 0; t < T; t++) {
        CP_WAIT(0);
        __syncthreads();
        if (t + 1 < T)
            issue(kBeg + (t + 1) * 32, (t & 1) ? As0 : As1, (t & 1) ? Bs0 : Bs1);
        float* Asb = (t & 1) ? As1 : As0;
        float* Bsb = (t & 1) ? Bs1 : Bs0;

#pragma unroll
        for (int ks = 0; ks < 4; ks++) {
            const int kcol = ks * 8 + 2 * tig;   // stored pos pair -> cols (k, k+4)
            uint32_t a[4][4];
#pragma unroll
            for (int mt = 0; mt < 4; mt++) {
                int r = wm + mt * 16 + gid;
                float2 u = *(const float2*)&Asb[r * 40 + kcol];
                float2 w = *(const float2*)&Asb[(r + 8) * 40 + kcol];
                a[mt][0] = fu(u.x); a[mt][2] = fu(u.y);
                a[mt][1] = fu(w.x); a[mt][3] = fu(w.y);
            }
            uint32_t b[4][2];
#pragma unroll
            for (int nt = 0; nt < 4; nt++) {
                int rn = wn + nt * 8 + gid;
                float2 v = *(const float2*)&Bsb[rn * 40 + kcol];
                b[nt][0] = fu(v.x); b[nt][1] = fu(v.y);
            }
#pragma unroll
            for (int mt = 0; mt < 4; mt++)
#pragma unroll
                for (int nt = 0; nt < 4; nt++)
                    mma8(c[mt][nt], a[mt], b[nt]);
        }
    }

#pragma unroll
    for (int mt = 0; mt < 4; mt++) {
#pragma unroll
        for (int nt = 0; nt < 4; nt++) {
#pragma unroll
            for (int e = 0; e < 4; e++) {
                int row = mBase + wm + mt * 16 + gid + ((e >> 1) << 3);
                int col = nBase + wn + nt * 8 + 2 * tig + (e & 1);
                float v = c[mt][nt][e];
                if (MODE == 0) {
                    v = rnd(v);
                    if (col < DM) {
                        if (row >= QSTART) g_Q[(size_t)(row - QSTART) * DM + col] = v;
                    } else if (col < 2 * DM) {
                        int ck = col - DM;
                        int c8 = ck & 7;
                        int p8 = (c8 < 4) ? 2 * c8 : 2 * c8 - 7;
                        g_Kp[(size_t)row * DM + (ck & ~7) + p8] = v;
                    } else {
                        g_V[(size_t)row * DM + (col - 2 * DM)] = v;
                    }
                } else {
                    if (row < M) atomicAdd(&C[(size_t)row * N + col], v);
                }
            }
        }
    }
}

// ============================================================================
// Fused qkv: 640 live GEMM tiles + 192 NS streaming blocks (10:3 interleave).
// ============================================================================
__global__ void __launch_bounds__(256, 2)
fused_qkv(const float* __restrict__ x, const float* __restrict__ W_NS) {
    extern __shared__ float sm[];
    const int bid = blockIdx.x;
    const int grp = bid / 13, rem = bid % 13;
    if (rem < 10) {
        const int g = grp * 10 + rem;       // 0..639
        int mt, nt;
        if (g < 384) { mt = 16 + g / 24; nt = g % 24; }            // rows>=2048: QKV
        else { int g2 = g - 384; mt = g2 / 16; nt = 8 + g2 % 16; } // rows<2048: KV only
        gemm_tile<0>((const float*)g_xr, (const float*)g_Wsr, nullptr,
                     4096, 3072, 1024, 0, 1024, mt * 128, nt * 128, sm);
    } else {
        const int ns  = grp * 3 + (rem - 10);   // 0..191
        const int tok = ns / 3;
        const int cb  = ns % 3;                 // 0=Q, 1=K, 2=V
        const int c4  = cb * 1024 + threadIdx.x * 4;

        const float* xr = x + (size_t)(L_S_C + tok) * DM;
        for (int i = threadIdx.x; i < DM; i += 256) sm[i] = xr[i];
        __syncthreads();

        const float* Wp = W_NS + (size_t)tok * DM * 3072 + c4;
        float4 acc = make_float4(0.f, 0.f, 0.f, 0.f);
#pragma unroll 8
        for (int d = 0; d < DM; d++) {
            float4 w = __ldcs((const float4*)(Wp + (size_t)d * 3072));
            float xv = sm[d];
            acc.x = fmaf(xv, w.x, acc.x);
            acc.y = fmaf(xv, w.y, acc.y);
            acc.z = fmaf(xv, w.z, acc.z);
            acc.w = fmaf(xv, w.w, acc.w);
        }
        float vals[4] = {rnd(acc.x), rnd(acc.y), rnd(acc.z), rnd(acc.w)};

        if (cb == 0) {
            *(float4*)(g_Q + (size_t)(QSTART + tok) * DM + c4) =
                make_float4(vals[0], vals[1], vals[2], vals[3]);
        } else if (cb == 1) {
            int ck = c4 - 1024;
            int b8 = ck & ~7, o0 = ck & 7;       // o0 in {0,4}
#pragma unroll
            for (int j = 0; j < 4; j++) {
                int c8 = o0 + j;
                int p8 = (c8 < 4) ? 2 * c8 : 2 * c8 - 7;
                g_Kp[(size_t)(L_S_C + tok) * DM + b8 + p8] = vals[j];
            }
        } else {
            *(float4*)(g_V + (size_t)(L_S_C + tok) * DM + (c4 - 2048)) =
                make_float4(vals[0], vals[1], vals[2], vals[3]);
        }
    }
}

// Output projection, split-K x2 (blockIdx.z = half), atomicAdd epilogue.
__global__ void __launch_bounds__(256, 2)
gemm_out(float* __restrict__ C) {
    extern __shared__ float sm[];
    gemm_tile<1>((const float*)g_AO, (const float*)g_Wor, C, LQ, 1024, 1024,
                 blockIdx.z * 512, 512, blockIdx.y * 128, blockIdx.x * 128, sm);
}

// ============================================================================
// Flash attention v4: 128 q-rows per CTA, 256 thr / 8 warps, Q frags in regs,
// permuted K / V^T -> LDS.64 frags, ONE barrier per k-iter.
// ============================================================================
__global__ void __launch_bounds__(256, 2)
attn_kernel() {
    extern __shared__ float sm[];
    float* Ps  = sm;              // [128][72] (Q staging, then P)
    float* KsA = sm + 9216;       // [64][72]
    float* KsB = sm + 13824;
    float* VsA = sm + 18432;
    float* VsB = sm + 23040;

    const int qtp = 16 - ((int)blockIdx.x >> 4);   // descending work size
    const int h   = blockIdx.x & 15;
    const int qb  = qtp * 128;
    const int tid  = threadIdx.x;
    const int warp = tid >> 5, lane = tid & 31;
    const int gid  = lane >> 2, tig = lane & 3;
    const int rq0  = warp * 16 + gid;

    auto loadKV = [&](int kt, float* Kd, float* Vd) {
        const float* kp = g_Kp + (size_t)kt * 64 * DM + h * DH;
        const float* vp = g_Vt + (size_t)h * DH * LK + kt * 64;
#pragma unroll
        for (int i = 0; i < 4; i++) {
            int idx = tid + i * 256;
            int r = idx >> 4, c4 = (idx & 15) << 2;
            cp16(&Kd[r * 72 + c4], kp + (size_t)r * DM + c4, 16);
            cp16(&Vd[r * 72 + c4], vp + (size_t)r * LK + c4, 16);
        }
        CP_COMMIT();
    };

    loadKV(0, KsA, VsA);

    // Stage Q (unpermuted) into Ps, extract register fragments.
    for (int i = tid; i < 128 * 16; i += 256) {
        int r = i >> 4, c4 = (i & 15) << 2;
        *(float4*)&Ps[r * 72 + c4] =
            *(const float4*)(g_Q + (size_t)(qb + r) * DM + h * DH + c4);
    }
    __syncthreads();
    uint32_t qa[8][4];
#pragma unroll
    for (int ks = 0; ks < 8; ks++) {
        qa[ks][0] = fu(Ps[rq0 * 72 + ks * 8 + tig] * 0.125f);
        qa[ks][2] = fu(Ps[rq0 * 72 + ks * 8 + tig + 4] * 0.125f);
        qa[ks][1] = fu(Ps[(rq0 + 8) * 72 + ks * 8 + tig] * 0.125f);
        qa[ks][3] = fu(Ps[(rq0 + 8) * 72 + ks * 8 + tig + 4] * 0.125f);
    }

    const int p0 = (tig < 2) ? 4 * tig     : 4 * tig - 7;   // pos of col 2tig
    const int p1 = (tig < 2) ? 4 * tig + 2 : 4 * tig - 5;   // pos of col 2tig+1

    float m0 = -1e30f, m1 = -1e30f, l0 = 0.f, l1 = 0.f;
    float o[8][4];
#pragma unroll
    for (int i = 0; i < 8; i++)
#pragma unroll
        for (int e = 0; e < 4; e++) o[i][e] = 0.f;

    const int nktFull = 34 + 2 * qtp;
    const int nkt = nktFull < 65 ? nktFull : 65;
    for (int kt = 0; kt < nkt; kt++) {
        CP_WAIT(0);
        __syncthreads();
        if (kt + 1 < nkt)
            loadKV(kt + 1, (kt & 1) ? KsA : KsB, (kt & 1) ? VsA : VsB);
        float* Ks = (kt & 1) ? KsB : KsA;
        float* Vs = (kt & 1) ? VsB : VsA;

        // S = Q @ K^T  (Q frags in regs, K frags LDS.64)
        float s[8][4];
#pragma unroll
        for (int i = 0; i < 8; i++)
#pragma unroll
            for (int e = 0; e < 4; e++) s[i][e] = 0.f;

#pragma unroll
        for (int ks = 0; ks < 8; ks++) {
            const int kcol = ks * 8 + 2 * tig;
#pragma unroll
            for (int nt = 0; nt < 8; nt++) {
                float2 bv = *(const float2*)&Ks[(nt * 8 + gid) * 72 + kcol];
                uint32_t bb[2] = {fu(bv.x), fu(bv.y)};
                mma8(s[nt], qa[ks], bb);
            }
        }

        // Causal mask on last two k-tiles
        if (kt >= nkt - 2) {
            const int off = kt * 64 - QSTART - qb;
#pragma unroll
            for (int nt = 0; nt < 8; nt++) {
#pragma unroll
                for (int e = 0; e < 4; e++) {
                    int kc  = nt * 8 + 2 * tig + (e & 1);
                    int rit = warp * 16 + gid + ((e >> 1) << 3);
                    if (kc + off > rit) s[nt][e] = -1e30f;
                }
            }
        }

        // Online softmax
        float rm0 = -1e30f, rm1 = -1e30f;
#pragma unroll
        for (int nt = 0; nt < 8; nt++) {
            rm0 = fmaxf(rm0, fmaxf(s[nt][0], s[nt][1]));
            rm1 = fmaxf(rm1, fmaxf(s[nt][2], s[nt][3]));
        }
        rm0 = fmaxf(rm0, __shfl_xor_sync(0xffffffffu, rm0, 1));
        rm0 = fmaxf(rm0, __shfl_xor_sync(0xffffffffu, rm0, 2));
        rm1 = fmaxf(rm1, __shfl_xor_sync(0xffffffffu, rm1, 1));
        rm1 = fmaxf(rm1, __shfl_xor_sync(0xffffffffu, rm1, 2));

        float mn0 = fmaxf(m0, rm0), mn1 = fmaxf(m1, rm1);
        float sc0 = __expf(m0 - mn0), sc1 = __expf(m1 - mn1);
        m0 = mn0; m1 = mn1;

        float rs0 = 0.f, rs1 = 0.f;
#pragma unroll
        for (int nt = 0; nt < 8; nt++) {
            s[nt][0] = __expf(s[nt][0] - m0); rs0 += s[nt][0];
            s[nt][1] = __expf(s[nt][1] - m0); rs0 += s[nt][1];
            s[nt][2] = __expf(s[nt][2] - m1); rs1 += s[nt][2];
            s[nt][3] = __expf(s[nt][3] - m1); rs1 += s[nt][3];
        }
        rs0 += __shfl_xor_sync(0xffffffffu, rs0, 1);
        rs0 += __shfl_xor_sync(0xffffffffu, rs0, 2);
        rs1 += __shfl_xor_sync(0xffffffffu, rs1, 1);
        rs1 += __shfl_xor_sync(0xffffffffu, rs1, 2);
        l0 = l0 * sc0 + rs0;
        l1 = l1 * sc1 + rs1;

#pragma unroll
        for (int dt = 0; dt < 8; dt++) {
            o[dt][0] *= sc0; o[dt][1] *= sc0;
            o[dt][2] *= sc1; o[dt][3] *= sc1;
        }

        // P -> Ps at permuted positions (warp-private rows), rounded tf32
#pragma unroll
        for (int nt = 0; nt < 8; nt++) {
            Ps[rq0 * 72 + nt * 8 + p0]       = rnd(s[nt][0]);
            Ps[rq0 * 72 + nt * 8 + p1]       = rnd(s[nt][1]);
            Ps[(rq0 + 8) * 72 + nt * 8 + p0] = rnd(s[nt][2]);
            Ps[(rq0 + 8) * 72 + nt * 8 + p1] = rnd(s[nt][3]);
        }
        __syncwarp();

        // O += P @ V   (P frags LDS.64, V^T frags LDS.64)
#pragma unroll
        for (int ks = 0; ks < 8; ks++) {
            const int kcol = ks * 8 + 2 * tig;
            float2 u = *(const float2*)&Ps[rq0 * 72 + kcol];
            float2 w = *(const float2*)&Ps[(rq0 + 8) * 72 + kcol];
            uint32_t a[4] = {fu(u.x), fu(w.x), fu(u.y), fu(w.y)};
#pragma unroll
            for (int dt = 0; dt < 8; dt++) {
                float2 bv = *(const float2*)&Vs[(dt * 8 + gid) * 72 + kcol];
                uint32_t bb[2] = {fu(bv.x), fu(bv.y)};
                mma8(o[dt], a, bb);
            }
        }
    }

    // Epilogue: write g_AO in k-permuted layout (matches g_Wor for gemm_out)
    const float il0 = 1.f / l0, il1 = 1.f / l1;
    const int qr0 = qb + rq0, qr1 = qb + rq0 + 8;
#pragma unroll
    for (int dt = 0; dt < 8; dt++) {
        int base = h * DH + dt * 8;
        if (qr0 < LQ) {
            g_AO[(size_t)qr0 * DM + base + p0] = rnd(o[dt][0] * il0);
            g_AO[(size_t)qr0 * DM + base + p1] = rnd(o[dt][1] * il0);
        }
        if (qr1 < LQ) {
            g_AO[(size_t)qr1 * DM + base + p0] = rnd(o[dt][2] * il1);
            g_AO[(size_t)qr1 * DM + base + p1] = rnd(o[dt][3] * il1);
        }
    }
}

// ============================================================================
extern "C" void kernel_launch(void* const* d_in, const int* in_sizes, int n_in,
                              void* d_out, int out_size) {
    const float* x     = (const float*)d_in[0];
    const float* W_S   = (const float*)d_in[1];
    const float* W_NS  = (const float*)d_in[2];
    const float* W_out = (const float*)d_in[3];
    float* out = (float*)d_out;
    (void)in_sizes; (void)n_in; (void)out_size;

    const int gemm_smem = 4 * 5120 * (int)sizeof(float);   // 81920
    const int attn_smem = 27648 * (int)sizeof(float);      // 110592

    cudaFuncSetAttribute(fused_qkv,   cudaFuncAttributeMaxDynamicSharedMemorySize, gemm_smem);
    cudaFuncSetAttribute(gemm_out,    cudaFuncAttributeMaxDynamicSharedMemorySize, gemm_smem);
    cudaFuncSetAttribute(attn_kernel, cudaFuncAttributeMaxDynamicSharedMemorySize, attn_smem);

    // 0) prep: round+permute x; transpose+round+permute W_S, W_out; zero d_out
    prep_x<<<512, 256>>>(x);
    prep_tr<<<dim3(3 * DM / 32, DM / 32), 256>>>(W_S, 0);
    prep_tr<<<dim3(DM / 32, DM / 32), 256>>>(W_out, 1);
    zeroC<<<(LQ * DM / 4 + 255) / 256, 256>>>(out);

    // 1+2) fused: live qkv GEMM tiles (640, K permuted in epilogue) + NS (192)
    fused_qkv<<<832, 256, gemm_smem>>>(x, W_NS);

    // 2b) repack V (transpose + token-permute)
    repack_Vt<<<dim3(LK / 32, DM / 32), 256>>>();

    // 3) attention: 17 q-pair tiles x 16 heads, longest first
    attn_kernel<<<17 * NH, 256, attn_smem>>>();

    // 4) output projection, split-K x2, atomic accumulate
    gemm_out<<<dim3(1024 / 128, (LQ + 127) / 128, 2), 256, gemm_smem>>>(out);
}

// round 10
// speedup vs baseline: 1.0220x; 1.0007x over previous
#include <cuda_runtime.h>
#include <cstdint>
#include <cstddef>

// Problem constants
#define L_S_C   4096
#define QSTART  2048
#define L_NS_C  64
#define LQ      2112
#define LK      4160
#define DM      1024
#define NH      16
#define DH      64

// Scratch (device globals). g_Q padded +64 rows for the clamped last q-block.
__device__ float g_Q[(size_t)(LQ + 64) * DM];
__device__ float g_V[(size_t)LK * DM];
__device__ float g_AO[(size_t)LQ * DM];          // k-permuted layout
__device__ float g_xr[(size_t)LK * DM];          // rounded x (row-major [m][k]), k-permuted
__device__ float g_Wsr[(size_t)(3 * DM) * DM];   // rounded W_S^T [n][k], k-permuted
__device__ float g_Wor[(size_t)DM * DM];         // rounded W_out^T [n][k], k-permuted
__device__ float g_Kp[(size_t)LK * DM];          // K, head-dim 8-block permuted
__device__ float g_Vt[(size_t)DM * LK];          // V^T [d][token], token 8-block permuted

// 8-block permutation: stored position p holds orig col sigma(p):
// sigma(2t)=t, sigma(2t+1)=t+4  -> stored order [0,4,1,5,2,6,3,7].
// Inverse: pos(c) = c<4 ? 2c : 2c-7.

__device__ __forceinline__ uint32_t f2tf(float x) {
    uint32_t r;
    asm("cvt.rna.tf32.f32 %0, %1;" : "=r"(r) : "f"(x));
    return r;
}
__device__ __forceinline__ float rnd(float x) { return __uint_as_float(f2tf(x)); }
__device__ __forceinline__ uint32_t fu(float x) { return __float_as_uint(x); }

__device__ __forceinline__ void mma8(float* c, const uint32_t* a, const uint32_t* b) {
    asm volatile(
        "mma.sync.aligned.m16n8k8.row.col.f32.tf32.tf32.f32 "
        "{%0,%1,%2,%3}, {%4,%5,%6,%7}, {%8,%9}, {%0,%1,%2,%3};\n"
        : "+f"(c[0]), "+f"(c[1]), "+f"(c[2]), "+f"(c[3])
        : "r"(a[0]), "r"(a[1]), "r"(a[2]), "r"(a[3]), "r"(b[0]), "r"(b[1]));
}

__device__ __forceinline__ void cp16(void* dst, const void* src, int sz) {
    uint32_t d = (uint32_t)__cvta_generic_to_shared(dst);
    asm volatile("cp.async.cg.shared.global [%0], [%1], 16, %2;\n"
                 :: "r"(d), "l"(src), "r"(sz));
}
#define CP_COMMIT()  asm volatile("cp.async.commit_group;\n")
#define CP_WAIT(n)   asm volatile("cp.async.wait_group %0;\n" :: "n"(n))

// ============================================================================
// Prep: round+permute x; transpose+round+permute W_S / W_out.
// ============================================================================
__global__ void __launch_bounds__(256)
prep_x(const float* __restrict__ x) {
    const int NT8 = (int)((size_t)LK * DM / 8);
    for (int i = blockIdx.x * blockDim.x + threadIdx.x; i < NT8;
         i += gridDim.x * blockDim.x) {
        const float4* s = (const float4*)x + 2 * i;
        float4 v0 = s[0], v1 = s[1];
        float4 w0 = make_float4(rnd(v0.x), rnd(v1.x), rnd(v0.y), rnd(v1.y));
        float4 w1 = make_float4(rnd(v0.z), rnd(v1.z), rnd(v0.w), rnd(v1.w));
        ((float4*)g_xr)[2 * i]     = w0;
        ((float4*)g_xr)[2 * i + 1] = w1;
    }
}

__global__ void __launch_bounds__(256)
prep_tr(const float* __restrict__ src, int which) {
    __shared__ float t[32][33];
    const int C = which ? DM : 3 * DM;
    float* dst = which ? g_Wor : g_Wsr;
    const int c0 = blockIdx.x * 32, r0 = blockIdx.y * 32;
    const int tx = threadIdx.x & 31, ty = threadIdx.x >> 5;
#pragma unroll
    for (int i = 0; i < 4; i++)
        t[ty + i * 8][tx] = rnd(src[(size_t)(r0 + ty + i * 8) * C + c0 + tx]);
    __syncthreads();
    const int tx8 = tx & 7;
    const int pk = (tx & ~7) + (tx8 < 4 ? 2 * tx8 : 2 * tx8 - 7);
#pragma unroll
    for (int i = 0; i < 4; i++)
        dst[(size_t)(c0 + ty + i * 8) * DM + r0 + pk] = t[tx][ty + i * 8];
}

// V transpose repack: [d][token], token 8-block permuted.
__global__ void __launch_bounds__(256)
repack_Vt() {
    __shared__ float t[32][33];
    const int tok0 = blockIdx.x * 32, d0 = blockIdx.y * 32;
    const int tx = threadIdx.x & 31, ty = threadIdx.x >> 5;
#pragma unroll
    for (int i = 0; i < 4; i++)
        t[ty + i * 8][tx] = g_V[(size_t)(tok0 + ty + i * 8) * DM + d0 + tx];
    __syncthreads();
    const int tx8 = tx & 7;
    const int ptok = (tx & ~7) + (tx8 < 4 ? 2 * tx8 : 2 * tx8 - 7);
#pragma unroll
    for (int i = 0; i < 4; i++)
        g_Vt[(size_t)(d0 + ty + i * 8) * LK + tok0 + ptok] = t[tx][ty + i * 8];
}

// Zero d_out for atomic-accumulating split-K output projection.
__global__ void __launch_bounds__(256)
zeroC(float* __restrict__ C) {
    int i = blockIdx.x * blockDim.x + threadIdx.x;
    if (i < LQ * DM / 4) ((float4*)C)[i] = make_float4(0.f, 0.f, 0.f, 0.f);
}

// ============================================================================
// tf32 warp-MMA GEMM tile (k-permuted operands -> LDS.64 fragments).
// Single barrier per k-iter: CP_WAIT(all) -> barrier -> issue(t+1) -> compute.
// Buffers: As0 @0, As1 @5120, Bs0 @10240, Bs1 @15360 (floats, stride 40).
// MODE 0: scatter rnd() into g_Q/g_Kp(permuted)/g_V. MODE 1: atomicAdd into C.
// ============================================================================
template <int MODE>
__device__ __forceinline__ void gemm_tile(const float* __restrict__ A,
                                          const float* __restrict__ Bt,
                                          float* __restrict__ C,
                                          int M, int N, int Ks, int kBeg, int kLen,
                                          int mBase, int nBase, float* sm) {
    float* As0 = sm;
    float* As1 = sm + 5120;
    float* Bs0 = sm + 10240;
    float* Bs1 = sm + 15360;

    const int tid  = threadIdx.x;
    const int warp = tid >> 5, lane = tid & 31;
    const int gid  = lane >> 2, tig = lane & 3;
    const int wm = (warp >> 2) * 64;
    const int wn = (warp & 3) * 32;

    const int ar = tid >> 3;
    const int ac = (tid & 7) << 2;

    float c[4][4][4];
#pragma unroll
    for (int i = 0; i < 4; i++)
#pragma unroll
        for (int j = 0; j < 4; j++)
#pragma unroll
            for (int e = 0; e < 4; e++) c[i][j][e] = 0.f;

    auto issue = [&](int k0, float* Asb, float* Bsb) {
#pragma unroll
        for (int i = 0; i < 4; i++) {
            int row = ar + i * 32;
            int grow = mBase + row;
            int ok = (MODE == 1) ? (grow < M) : 1;
            const float* asrc = A + (size_t)(ok ? grow : 0) * Ks + k0 + ac;
            cp16(&Asb[row * 40 + ac], asrc, ok ? 16 : 0);
            const float* bsrc = Bt + (size_t)(nBase + row) * Ks + k0 + ac;
            cp16(&Bsb[row * 40 + ac], bsrc, 16);
        }
        CP_COMMIT();
    };

    issue(kBeg, As0, Bs0);

    const int T = kLen / 32;
    for (int t = 0; t < T; t++) {
        CP_WAIT(0);
        __syncthreads();
        if (t + 1 < T)
            issue(kBeg + (t + 1) * 32, (t & 1) ? As0 : As1, (t & 1) ? Bs0 : Bs1);
        float* Asb = (t & 1) ? As1 : As0;
        float* Bsb = (t & 1) ? Bs1 : Bs0;

#pragma unroll
        for (int ks = 0; ks < 4; ks++) {
            const int kcol = ks * 8 + 2 * tig;   // stored pos pair -> cols (k, k+4)
            uint32_t a[4][4];
#pragma unroll
            for (int mt = 0; mt < 4; mt++) {
                int r = wm + mt * 16 + gid;
                float2 u = *(const float2*)&Asb[r * 40 + kcol];
                float2 w = *(const float2*)&Asb[(r + 8) * 40 + kcol];
                a[mt][0] = fu(u.x); a[mt][2] = fu(u.y);
                a[mt][1] = fu(w.x); a[mt][3] = fu(w.y);
            }
            uint32_t b[4][2];
#pragma unroll
            for (int nt = 0; nt < 4; nt++) {
                int rn = wn + nt * 8 + gid;
                float2 v = *(const float2*)&Bsb[rn * 40 + kcol];
                b[nt][0] = fu(v.x); b[nt][1] = fu(v.y);
            }
#pragma unroll
            for (int mt = 0; mt < 4; mt++)
#pragma unroll
                for (int nt = 0; nt < 4; nt++)
                    mma8(c[mt][nt], a[mt], b[nt]);
        }
    }

#pragma unroll
    for (int mt = 0; mt < 4; mt++) {
#pragma unroll
        for (int nt = 0; nt < 4; nt++) {
#pragma unroll
            for (int e = 0; e < 4; e++) {
                int row = mBase + wm + mt * 16 + gid + ((e >> 1) << 3);
                int col = nBase + wn + nt * 8 + 2 * tig + (e & 1);
                float v = c[mt][nt][e];
                if (MODE == 0) {
                    v = rnd(v);
                    if (col < DM) {
                        if (row >= QSTART) g_Q[(size_t)(row - QSTART) * DM + col] = v;
                    } else if (col < 2 * DM) {
                        int ck = col - DM;
                        int c8 = ck & 7;
                        int p8 = (c8 < 4) ? 2 * c8 : 2 * c8 - 7;
                        g_Kp[(size_t)row * DM + (ck & ~7) + p8] = v;
                    } else {
                        g_V[(size_t)row * DM + (col - 2 * DM)] = v;
                    }
                } else {
                    if (row < M) atomicAdd(&C[(size_t)row * N + col], v);
                }
            }
        }
    }
}

// ============================================================================
// Fused qkv: 640 live GEMM tiles + 192 NS streaming blocks (10:3 interleave).
// ============================================================================
__global__ void __launch_bounds__(256, 2)
fused_qkv(const float* __restrict__ x, const float* __restrict__ W_NS) {
    extern __shared__ float sm[];
    const int bid = blockIdx.x;
    const int grp = bid / 13, rem = bid % 13;
    if (rem < 10) {
        const int g = grp * 10 + rem;       // 0..639
        int mt, nt;
        if (g < 384) { mt = 16 + g / 24; nt = g % 24; }            // rows>=2048: QKV
        else { int g2 = g - 384; mt = g2 / 16; nt = 8 + g2 % 16; } // rows<2048: KV only
        gemm_tile<0>((const float*)g_xr, (const float*)g_Wsr, nullptr,
                     4096, 3072, 1024, 0, 1024, mt * 128, nt * 128, sm);
    } else {
        const int ns  = grp * 3 + (rem - 10);   // 0..191
        const int tok = ns / 3;
        const int cb  = ns % 3;                 // 0=Q, 1=K, 2=V
        const int c4  = cb * 1024 + threadIdx.x * 4;

        const float* xr = x + (size_t)(L_S_C + tok) * DM;
        for (int i = threadIdx.x; i < DM; i += 256) sm[i] = xr[i];
        __syncthreads();

        const float* Wp = W_NS + (size_t)tok * DM * 3072 + c4;
        float4 acc = make_float4(0.f, 0.f, 0.f, 0.f);
#pragma unroll 8
        for (int d = 0; d < DM; d++) {
            float4 w = __ldcs((const float4*)(Wp + (size_t)d * 3072));
            float xv = sm[d];
            acc.x = fmaf(xv, w.x, acc.x);
            acc.y = fmaf(xv, w.y, acc.y);
            acc.z = fmaf(xv, w.z, acc.z);
            acc.w = fmaf(xv, w.w, acc.w);
        }
        float vals[4] = {rnd(acc.x), rnd(acc.y), rnd(acc.z), rnd(acc.w)};

        if (cb == 0) {
            *(float4*)(g_Q + (size_t)(QSTART + tok) * DM + c4) =
                make_float4(vals[0], vals[1], vals[2], vals[3]);
        } else if (cb == 1) {
            int ck = c4 - 1024;
            int b8 = ck & ~7, o0 = ck & 7;       // o0 in {0,4}
#pragma unroll
            for (int j = 0; j < 4; j++) {
                int c8 = o0 + j;
                int p8 = (c8 < 4) ? 2 * c8 : 2 * c8 - 7;
                g_Kp[(size_t)(L_S_C + tok) * DM + b8 + p8] = vals[j];
            }
        } else {
            *(float4*)(g_V + (size_t)(L_S_C + tok) * DM + (c4 - 2048)) =
                make_float4(vals[0], vals[1], vals[2], vals[3]);
        }
    }
}

// Output projection, split-K x2 (blockIdx.z = half), atomicAdd epilogue.
__global__ void __launch_bounds__(256, 2)
gemm_out(float* __restrict__ C) {
    extern __shared__ float sm[];
    gemm_tile<1>((const float*)g_AO, (const float*)g_Wor, C, LQ, 1024, 1024,
                 blockIdx.z * 512, 512, blockIdx.y * 128, blockIdx.x * 128, sm);
}

// ============================================================================
// Flash attention v4: 128 q-rows per CTA, 256 thr / 8 warps, Q frags in regs,
// permuted K / V^T -> LDS.64 frags, ONE barrier per k-iter.
// ============================================================================
__global__ void __launch_bounds__(256, 2)
attn_kernel() {
    extern __shared__ float sm[];
    float* Ps  = sm;              // [128][72] (Q staging, then P)
    float* KsA = sm + 9216;       // [64][72]
    float* KsB = sm + 13824;
    float* VsA = sm + 18432;
    float* VsB = sm + 23040;

    const int qtp = 16 - ((int)blockIdx.x >> 4);   // descending work size
    const int h   = blockIdx.x & 15;
    const int qb  = qtp * 128;
    const int tid  = threadIdx.x;
    const int warp = tid >> 5, lane = tid & 31;
    const int gid  = lane >> 2, tig = lane & 3;
    const int rq0  = warp * 16 + gid;

    auto loadKV = [&](int kt, float* Kd, float* Vd) {
        const float* kp = g_Kp + (size_t)kt * 64 * DM + h * DH;
        const float* vp = g_Vt + (size_t)h * DH * LK + kt * 64;
#pragma unroll
        for (int i = 0; i < 4; i++) {
            int idx = tid + i * 256;
            int r = idx >> 4, c4 = (idx & 15) << 2;
            cp16(&Kd[r * 72 + c4], kp + (size_t)r * DM + c4, 16);
            cp16(&Vd[r * 72 + c4], vp + (size_t)r * LK + c4, 16);
        }
        CP_COMMIT();
    };

    loadKV(0, KsA, VsA);

    // Stage Q (unpermuted) into Ps, extract register fragments.
    for (int i = tid; i < 128 * 16; i += 256) {
        int r = i >> 4, c4 = (i & 15) << 2;
        *(float4*)&Ps[r * 72 + c4] =
            *(const float4*)(g_Q + (size_t)(qb + r) * DM + h * DH + c4);
    }
    __syncthreads();
    uint32_t qa[8][4];
#pragma unroll
    for (int ks = 0; ks < 8; ks++) {
        qa[ks][0] = fu(Ps[rq0 * 72 + ks * 8 + tig] * 0.125f);
        qa[ks][2] = fu(Ps[rq0 * 72 + ks * 8 + tig + 4] * 0.125f);
        qa[ks][1] = fu(Ps[(rq0 + 8) * 72 + ks * 8 + tig] * 0.125f);
        qa[ks][3] = fu(Ps[(rq0 + 8) * 72 + ks * 8 + tig + 4] * 0.125f);
    }

    const int p0 = (tig < 2) ? 4 * tig     : 4 * tig - 7;   // pos of col 2tig
    const int p1 = (tig < 2) ? 4 * tig + 2 : 4 * tig - 5;   // pos of col 2tig+1

    float m0 = -1e30f, m1 = -1e30f, l0 = 0.f, l1 = 0.f;
    float o[8][4];
#pragma unroll
    for (int i = 0; i < 8; i++)
#pragma unroll
        for (int e = 0; e < 4; e++) o[i][e] = 0.f;

    const int nktFull = 34 + 2 * qtp;
    const int nkt = nktFull < 65 ? nktFull : 65;
    for (int kt = 0; kt < nkt; kt++) {
        CP_WAIT(0);
        __syncthreads();
        if (kt + 1 < nkt)
            loadKV(kt + 1, (kt & 1) ? KsA : KsB, (kt & 1) ? VsA : VsB);
        float* Ks = (kt & 1) ? KsB : KsA;
        float* Vs = (kt & 1) ? VsB : VsA;

        // S = Q @ K^T  (Q frags in regs, K frags LDS.64)
        float s[8][4];
#pragma unroll
        for (int i = 0; i < 8; i++)
#pragma unroll
            for (int e = 0; e < 4; e++) s[i][e] = 0.f;

#pragma unroll
        for (int ks = 0; ks < 8; ks++) {
            const int kcol = ks * 8 + 2 * tig;
#pragma unroll
            for (int nt = 0; nt < 8; nt++) {
                float2 bv = *(const float2*)&Ks[(nt * 8 + gid) * 72 + kcol];
                uint32_t bb[2] = {fu(bv.x), fu(bv.y)};
                mma8(s[nt], qa[ks], bb);
            }
        }

        // Causal mask on last two k-tiles
        if (kt >= nkt - 2) {
            const int off = kt * 64 - QSTART - qb;
#pragma unroll
            for (int nt = 0; nt < 8; nt++) {
#pragma unroll
                for (int e = 0; e < 4; e++) {
                    int kc  = nt * 8 + 2 * tig + (e & 1);
                    int rit = warp * 16 + gid + ((e >> 1) << 3);
                    if (kc + off > rit) s[nt][e] = -1e30f;
                }
            }
        }

        // Online softmax
        float rm0 = -1e30f, rm1 = -1e30f;
#pragma unroll
        for (int nt = 0; nt < 8; nt++) {
            rm0 = fmaxf(rm0, fmaxf(s[nt][0], s[nt][1]));
            rm1 = fmaxf(rm1, fmaxf(s[nt][2], s[nt][3]));
        }
        rm0 = fmaxf(rm0, __shfl_xor_sync(0xffffffffu, rm0, 1));
        rm0 = fmaxf(rm0, __shfl_xor_sync(0xffffffffu, rm0, 2));
        rm1 = fmaxf(rm1, __shfl_xor_sync(0xffffffffu, rm1, 1));
        rm1 = fmaxf(rm1, __shfl_xor_sync(0xffffffffu, rm1, 2));

        float mn0 = fmaxf(m0, rm0), mn1 = fmaxf(m1, rm1);
        float sc0 = __expf(m0 - mn0), sc1 = __expf(m1 - mn1);
        m0 = mn0; m1 = mn1;

        float rs0 = 0.f, rs1 = 0.f;
#pragma unroll
        for (int nt = 0; nt < 8; nt++) {
            s[nt][0] = __expf(s[nt][0] - m0); rs0 += s[nt][0];
            s[nt][1] = __expf(s[nt][1] - m0); rs0 += s[nt][1];
            s[nt][2] = __expf(s[nt][2] - m1); rs1 += s[nt][2];
            s[nt][3] = __expf(s[nt][3] - m1); rs1 += s[nt][3];
        }
        rs0 += __shfl_xor_sync(0xffffffffu, rs0, 1);
        rs0 += __shfl_xor_sync(0xffffffffu, rs0, 2);
        rs1 += __shfl_xor_sync(0xffffffffu, rs1, 1);
        rs1 += __shfl_xor_sync(0xffffffffu, rs1, 2);
        l0 = l0 * sc0 + rs0;
        l1 = l1 * sc1 + rs1;

#pragma unroll
        for (int dt = 0; dt < 8; dt++) {
            o[dt][0] *= sc0; o[dt][1] *= sc0;
            o[dt][2] *= sc1; o[dt][3] *= sc1;
        }

        // P -> Ps at permuted positions (warp-private rows), rounded tf32
#pragma unroll
        for (int nt = 0; nt < 8; nt++) {
            Ps[rq0 * 72 + nt * 8 + p0]       = rnd(s[nt][0]);
            Ps[rq0 * 72 + nt * 8 + p1]       = rnd(s[nt][1]);
            Ps[(rq0 + 8) * 72 + nt * 8 + p0] = rnd(s[nt][2]);
            Ps[(rq0 + 8) * 72 + nt * 8 + p1] = rnd(s[nt][3]);
        }
        __syncwarp();

        // O += P @ V   (P frags LDS.64, V^T frags LDS.64)
#pragma unroll
        for (int ks = 0; ks < 8; ks++) {
            const int kcol = ks * 8 + 2 * tig;
            float2 u = *(const float2*)&Ps[rq0 * 72 + kcol];
            float2 w = *(const float2*)&Ps[(rq0 + 8) * 72 + kcol];
            uint32_t a[4] = {fu(u.x), fu(w.x), fu(u.y), fu(w.y)};
#pragma unroll
            for (int dt = 0; dt < 8; dt++) {
                float2 bv = *(const float2*)&Vs[(dt * 8 + gid) * 72 + kcol];
                uint32_t bb[2] = {fu(bv.x), fu(bv.y)};
                mma8(o[dt], a, bb);
            }
        }
    }

    // Epilogue: write g_AO in k-permuted layout (matches g_Wor for gemm_out)
    const float il0 = 1.f / l0, il1 = 1.f / l1;
    const int qr0 = qb + rq0, qr1 = qb + rq0 + 8;
#pragma unroll
    for (int dt = 0; dt < 8; dt++) {
        int base = h * DH + dt * 8;
        if (qr0 < LQ) {
            g_AO[(size_t)qr0 * DM + base + p0] = rnd(o[dt][0] * il0);
            g_AO[(size_t)qr0 * DM + base + p1] = rnd(o[dt][1] * il0);
        }
        if (qr1 < LQ) {
            g_AO[(size_t)qr1 * DM + base + p0] = rnd(o[dt][2] * il1);
            g_AO[(size_t)qr1 * DM + base + p1] = rnd(o[dt][3] * il1);
        }
    }
}

// ============================================================================
extern "C" void kernel_launch(void* const* d_in, const int* in_sizes, int n_in,
                              void* d_out, int out_size) {
    const float* x     = (const float*)d_in[0];
    const float* W_S   = (const float*)d_in[1];
    const float* W_NS  = (const float*)d_in[2];
    const float* W_out = (const float*)d_in[3];
    float* out = (float*)d_out;
    (void)in_sizes; (void)n_in; (void)out_size;

    const int gemm_smem = 4 * 5120 * (int)sizeof(float);   // 81920
    const int attn_smem = 27648 * (int)sizeof(float);      // 110592

    cudaFuncSetAttribute(fused_qkv,   cudaFuncAttributeMaxDynamicSharedMemorySize, gemm_smem);
    cudaFuncSetAttribute(gemm_out,    cudaFuncAttributeMaxDynamicSharedMemorySize, gemm_smem);
    cudaFuncSetAttribute(attn_kernel, cudaFuncAttributeMaxDynamicSharedMemorySize, attn_smem);

    // 0) prep: round+permute x; transpose+round+permute W_S, W_out; zero d_out
    prep_x<<<512, 256>>>(x);
    prep_tr<<<dim3(3 * DM / 32, DM / 32), 256>>>(W_S, 0);
    prep_tr<<<dim3(DM / 32, DM / 32), 256>>>(W_out, 1);
    zeroC<<<(LQ * DM / 4 + 255) / 256, 256>>>(out);

    // 1+2) fused: live qkv GEMM tiles (640, K permuted in epilogue) + NS (192)
    fused_qkv<<<832, 256, gemm_smem>>>(x, W_NS);

    // 2b) repack V (transpose + token-permute)
    repack_Vt<<<dim3(LK / 32, DM / 32), 256>>>();

    // 3) attention: 17 q-pair tiles x 16 heads, longest first
    attn_kernel<<<17 * NH, 256, attn_smem>>>();

    // 4) output projection, split-K x2, atomic accumulate
    gemm_out<<<dim3(1024 / 128, (LQ + 127) / 128, 2), 256, gemm_smem>>>(out);
}

// round 11
// speedup vs baseline: 1.0386x; 1.0162x over previous
#include <cuda_runtime.h>
#include <cstdint>
#include <cstddef>

// Problem constants
#define L_S_C   4096
#define QSTART  2048
#define L_NS_C  64
#define LQ      2112
#define LK      4160
#define DM      1024
#define NH      16
#define DH      64

// Scratch (device globals). g_Q padded +64 rows for the clamped last q-block.
__device__ float g_Q[(size_t)(LQ + 64) * DM];
__device__ float g_V[(size_t)LK * DM];
__device__ float g_AO[(size_t)LQ * DM];          // k-permuted layout
__device__ float g_xr[(size_t)LK * DM];          // rounded x (row-major [m][k]), k-permuted
__device__ float g_Wsr[(size_t)(3 * DM) * DM];   // rounded W_S^T [n][k], k-permuted
__device__ float g_Wor[(size_t)DM * DM];         // rounded W_out^T [n][k], k-permuted
__device__ float g_Kp[(size_t)LK * DM];          // K, head-dim 8-block permuted
__device__ float g_Vt[(size_t)DM * LK];          // V^T [d][token], token 8-block permuted

// 8-block permutation: stored position p holds orig col sigma(p):
// sigma(2t)=t, sigma(2t+1)=t+4  -> stored order [0,4,1,5,2,6,3,7].
// Inverse: pos(c) = c<4 ? 2c : 2c-7.

__device__ __forceinline__ uint32_t f2tf(float x) {
    uint32_t r;
    asm("cvt.rna.tf32.f32 %0, %1;" : "=r"(r) : "f"(x));
    return r;
}
__device__ __forceinline__ float rnd(float x) { return __uint_as_float(f2tf(x)); }
__device__ __forceinline__ uint32_t fu(float x) { return __float_as_uint(x); }

__device__ __forceinline__ void mma8(float* c, const uint32_t* a, const uint32_t* b) {
    asm volatile(
        "mma.sync.aligned.m16n8k8.row.col.f32.tf32.tf32.f32 "
        "{%0,%1,%2,%3}, {%4,%5,%6,%7}, {%8,%9}, {%0,%1,%2,%3};\n"
        : "+f"(c[0]), "+f"(c[1]), "+f"(c[2]), "+f"(c[3])
        : "r"(a[0]), "r"(a[1]), "r"(a[2]), "r"(a[3]), "r"(b[0]), "r"(b[1]));
}

__device__ __forceinline__ void cp16(void* dst, const void* src, int sz) {
    uint32_t d = (uint32_t)__cvta_generic_to_shared(dst);
    asm volatile("cp.async.cg.shared.global [%0], [%1], 16, %2;\n"
                 :: "r"(d), "l"(src), "r"(sz));
}
#define CP_COMMIT()  asm volatile("cp.async.commit_group;\n")
#define CP_WAIT(n)   asm volatile("cp.async.wait_group %0;\n" :: "n"(n))

// ============================================================================
// Prep: round+permute x; transpose+round+permute W_S / W_out.
// ============================================================================
__global__ void __launch_bounds__(256)
prep_x(const float* __restrict__ x) {
    const int NT8 = (int)((size_t)LK * DM / 8);
    for (int i = blockIdx.x * blockDim.x + threadIdx.x; i < NT8;
         i += gridDim.x * blockDim.x) {
        const float4* s = (const float4*)x + 2 * i;
        float4 v0 = s[0], v1 = s[1];
        float4 w0 = make_float4(rnd(v0.x), rnd(v1.x), rnd(v0.y), rnd(v1.y));
        float4 w1 = make_float4(rnd(v0.z), rnd(v1.z), rnd(v0.w), rnd(v1.w));
        ((float4*)g_xr)[2 * i]     = w0;
        ((float4*)g_xr)[2 * i + 1] = w1;
    }
}

__global__ void __launch_bounds__(256)
prep_tr(const float* __restrict__ src, int which) {
    __shared__ float t[32][33];
    const int C = which ? DM : 3 * DM;
    float* dst = which ? g_Wor : g_Wsr;
    const int c0 = blockIdx.x * 32, r0 = blockIdx.y * 32;
    const int tx = threadIdx.x & 31, ty = threadIdx.x >> 5;
#pragma unroll
    for (int i = 0; i < 4; i++)
        t[ty + i * 8][tx] = rnd(src[(size_t)(r0 + ty + i * 8) * C + c0 + tx]);
    __syncthreads();
    const int tx8 = tx & 7;
    const int pk = (tx & ~7) + (tx8 < 4 ? 2 * tx8 : 2 * tx8 - 7);
#pragma unroll
    for (int i = 0; i < 4; i++)
        dst[(size_t)(c0 + ty + i * 8) * DM + r0 + pk] = t[tx][ty + i * 8];
}

// V transpose repack: [d][token], token 8-block permuted.
__global__ void __launch_bounds__(256)
repack_Vt() {
    __shared__ float t[32][33];
    const int tok0 = blockIdx.x * 32, d0 = blockIdx.y * 32;
    const int tx = threadIdx.x & 31, ty = threadIdx.x >> 5;
#pragma unroll
    for (int i = 0; i < 4; i++)
        t[ty + i * 8][tx] = g_V[(size_t)(tok0 + ty + i * 8) * DM + d0 + tx];
    __syncthreads();
    const int tx8 = tx & 7;
    const int ptok = (tx & ~7) + (tx8 < 4 ? 2 * tx8 : 2 * tx8 - 7);
#pragma unroll
    for (int i = 0; i < 4; i++)
        g_Vt[(size_t)(d0 + ty + i * 8) * LK + tok0 + ptok] = t[tx][ty + i * 8];
}

// Zero d_out for atomic-accumulating split-K output projection.
__global__ void __launch_bounds__(256)
zeroC(float* __restrict__ C) {
    int i = blockIdx.x * blockDim.x + threadIdx.x;
    if (i < LQ * DM / 4) ((float4*)C)[i] = make_float4(0.f, 0.f, 0.f, 0.f);
}

// ============================================================================
// tf32 warp-MMA GEMM tile (k-permuted operands -> LDS.64 fragments).
// Single barrier per k-iter: CP_WAIT(all) -> barrier -> issue(t+1) -> compute.
// Buffers: As0 @0, As1 @5120, Bs0 @10240, Bs1 @15360 (floats, stride 40).
// MODE 0: scatter rnd() into g_Q/g_Kp(permuted)/g_V. MODE 1: atomicAdd into C.
// ============================================================================
template <int MODE>
__device__ __forceinline__ void gemm_tile(const float* __restrict__ A,
                                          const float* __restrict__ Bt,
                                          float* __restrict__ C,
                                          int M, int N, int Ks, int kBeg, int kLen,
                                          int mBase, int nBase, float* sm) {
    float* As0 = sm;
    float* As1 = sm + 5120;
    float* Bs0 = sm + 10240;
    float* Bs1 = sm + 15360;

    const int tid  = threadIdx.x;
    const int warp = tid >> 5, lane = tid & 31;
    const int gid  = lane >> 2, tig = lane & 3;
    const int wm = (warp >> 2) * 64;
    const int wn = (warp & 3) * 32;

    const int ar = tid >> 3;
    const int ac = (tid & 7) << 2;

    float c[4][4][4];
#pragma unroll
    for (int i = 0; i < 4; i++)
#pragma unroll
        for (int j = 0; j < 4; j++)
#pragma unroll
            for (int e = 0; e < 4; e++) c[i][j][e] = 0.f;

    auto issue = [&](int k0, float* Asb, float* Bsb) {
#pragma unroll
        for (int i = 0; i < 4; i++) {
            int row = ar + i * 32;
            int grow = mBase + row;
            int ok = (MODE == 1) ? (grow < M) : 1;
            const float* asrc = A + (size_t)(ok ? grow : 0) * Ks + k0 + ac;
            cp16(&Asb[row * 40 + ac], asrc, ok ? 16 : 0);
            const float* bsrc = Bt + (size_t)(nBase + row) * Ks + k0 + ac;
            cp16(&Bsb[row * 40 + ac], bsrc, 16);
        }
        CP_COMMIT();
    };

    issue(kBeg, As0, Bs0);

    const int T = kLen / 32;
    for (int t = 0; t < T; t++) {
        CP_WAIT(0);
        __syncthreads();
        if (t + 1 < T)
            issue(kBeg + (t + 1) * 32, (t & 1) ? As0 : As1, (t & 1) ? Bs0 : Bs1);
        float* Asb = (t & 1) ? As1 : As0;
        float* Bsb = (t & 1) ? Bs1 : Bs0;

#pragma unroll
        for (int ks = 0; ks < 4; ks++) {
            const int kcol = ks * 8 + 2 * tig;   // stored pos pair -> cols (k, k+4)
            uint32_t a[4][4];
#pragma unroll
            for (int mt = 0; mt < 4; mt++) {
                int r = wm + mt * 16 + gid;
                float2 u = *(const float2*)&Asb[r * 40 + kcol];
                float2 w = *(const float2*)&Asb[(r + 8) * 40 + kcol];
                a[mt][0] = fu(u.x); a[mt][2] = fu(u.y);
                a[mt][1] = fu(w.x); a[mt][3] = fu(w.y);
            }
            uint32_t b[4][2];
#pragma unroll
            for (int nt = 0; nt < 4; nt++) {
                int rn = wn + nt * 8 + gid;
                float2 v = *(const float2*)&Bsb[rn * 40 + kcol];
                b[nt][0] = fu(v.x); b[nt][1] = fu(v.y);
            }
#pragma unroll
            for (int mt = 0; mt < 4; mt++)
#pragma unroll
                for (int nt = 0; nt < 4; nt++)
                    mma8(c[mt][nt], a[mt], b[nt]);
        }
    }

#pragma unroll
    for (int mt = 0; mt < 4; mt++) {
#pragma unroll
        for (int nt = 0; nt < 4; nt++) {
#pragma unroll
            for (int e = 0; e < 4; e++) {
                int row = mBase + wm + mt * 16 + gid + ((e >> 1) << 3);
                int col = nBase + wn + nt * 8 + 2 * tig + (e & 1);
                float v = c[mt][nt][e];
                if (MODE == 0) {
                    v = rnd(v);
                    if (col < DM) {
                        if (row >= QSTART) g_Q[(size_t)(row - QSTART) * DM + col] = v;
                    } else if (col < 2 * DM) {
                        int ck = col - DM;
                        int c8 = ck & 7;
                        int p8 = (c8 < 4) ? 2 * c8 : 2 * c8 - 7;
                        g_Kp[(size_t)row * DM + (ck & ~7) + p8] = v;
                    } else {
                        g_V[(size_t)row * DM + (col - 2 * DM)] = v;
                    }
                } else {
                    if (row < M) atomicAdd(&C[(size_t)row * N + col], v);
                }
            }
        }
    }
}

// ============================================================================
// Fused qkv: 640 live GEMM tiles + 192 NS streaming blocks (10:3 interleave).
// ============================================================================
__global__ void __launch_bounds__(256, 2)
fused_qkv(const float* __restrict__ x, const float* __restrict__ W_NS) {
    extern __shared__ float sm[];
    const int bid = blockIdx.x;
    const int grp = bid / 13, rem = bid % 13;
    if (rem < 10) {
        const int g = grp * 10 + rem;       // 0..639
        int mt, nt;
        if (g < 384) { mt = 16 + g / 24; nt = g % 24; }            // rows>=2048: QKV
        else { int g2 = g - 384; mt = g2 / 16; nt = 8 + g2 % 16; } // rows<2048: KV only
        gemm_tile<0>((const float*)g_xr, (const float*)g_Wsr, nullptr,
                     4096, 3072, 1024, 0, 1024, mt * 128, nt * 128, sm);
    } else {
        const int ns  = grp * 3 + (rem - 10);   // 0..191
        const int tok = ns / 3;
        const int cb  = ns % 3;                 // 0=Q, 1=K, 2=V
        const int c4  = cb * 1024 + threadIdx.x * 4;

        const float* xr = x + (size_t)(L_S_C + tok) * DM;
        for (int i = threadIdx.x; i < DM; i += 256) sm[i] = xr[i];
        __syncthreads();

        const float* Wp = W_NS + (size_t)tok * DM * 3072 + c4;
        float4 acc = make_float4(0.f, 0.f, 0.f, 0.f);
#pragma unroll 8
        for (int d = 0; d < DM; d++) {
            float4 w = __ldcs((const float4*)(Wp + (size_t)d * 3072));
            float xv = sm[d];
            acc.x = fmaf(xv, w.x, acc.x);
            acc.y = fmaf(xv, w.y, acc.y);
            acc.z = fmaf(xv, w.z, acc.z);
            acc.w = fmaf(xv, w.w, acc.w);
        }
        float vals[4] = {rnd(acc.x), rnd(acc.y), rnd(acc.z), rnd(acc.w)};

        if (cb == 0) {
            *(float4*)(g_Q + (size_t)(QSTART + tok) * DM + c4) =
                make_float4(vals[0], vals[1], vals[2], vals[3]);
        } else if (cb == 1) {
            int ck = c4 - 1024;
            int b8 = ck & ~7, o0 = ck & 7;       // o0 in {0,4}
#pragma unroll
            for (int j = 0; j < 4; j++) {
                int c8 = o0 + j;
                int p8 = (c8 < 4) ? 2 * c8 : 2 * c8 - 7;
                g_Kp[(size_t)(L_S_C + tok) * DM + b8 + p8] = vals[j];
            }
        } else {
            *(float4*)(g_V + (size_t)(L_S_C + tok) * DM + (c4 - 2048)) =
                make_float4(vals[0], vals[1], vals[2], vals[3]);
        }
    }
}

// Output projection, split-K x2 (blockIdx.z = half), atomicAdd epilogue.
__global__ void __launch_bounds__(256, 2)
gemm_out(float* __restrict__ C) {
    extern __shared__ float sm[];
    gemm_tile<1>((const float*)g_AO, (const float*)g_Wor, C, LQ, 1024, 1024,
                 blockIdx.z * 512, 512, blockIdx.y * 128, blockIdx.x * 128, sm);
}

// ============================================================================
// Flash attention v5: deferred-PV software pipeline. Iter t executes
// S(t) MMAs, then (O *= sc_saved; PV(t-1)) -- two independent MMA phases
// back-to-back -- then prefetch(t+1), then softmax(t) producing P(t)+sc.
// Bit-identical math to v4, just time-shifted. 128 q-rows/CTA, 256 thr.
// ============================================================================
__global__ void __launch_bounds__(256, 2)
attn_kernel() {
    extern __shared__ float sm[];
    float* Ps  = sm;              // [128][72] (Q staging, then P)
    float* KsA = sm + 9216;       // [64][72]
    float* KsB = sm + 13824;
    float* VsA = sm + 18432;
    float* VsB = sm + 23040;

    const int qtp = 16 - ((int)blockIdx.x >> 4);   // descending work size
    const int h   = blockIdx.x & 15;
    const int qb  = qtp * 128;
    const int tid  = threadIdx.x;
    const int warp = tid >> 5, lane = tid & 31;
    const int gid  = lane >> 2, tig = lane & 3;
    const int rq0  = warp * 16 + gid;

    auto loadKV = [&](int kt, float* Kd, float* Vd) {
        const float* kp = g_Kp + (size_t)kt * 64 * DM + h * DH;
        const float* vp = g_Vt + (size_t)h * DH * LK + kt * 64;
#pragma unroll
        for (int i = 0; i < 4; i++) {
            int idx = tid + i * 256;
            int r = idx >> 4, c4 = (idx & 15) << 2;
            cp16(&Kd[r * 72 + c4], kp + (size_t)r * DM + c4, 16);
            cp16(&Vd[r * 72 + c4], vp + (size_t)r * LK + c4, 16);
        }
        CP_COMMIT();
    };

    loadKV(0, KsA, VsA);

    // Stage Q (unpermuted) into Ps, extract register fragments (warp-own rows).
    for (int i = tid; i < 128 * 16; i += 256) {
        int r = i >> 4, c4 = (i & 15) << 2;
        *(float4*)&Ps[r * 72 + c4] =
            *(const float4*)(g_Q + (size_t)(qb + r) * DM + h * DH + c4);
    }
    __syncthreads();
    uint32_t qa[8][4];
#pragma unroll
    for (int ks = 0; ks < 8; ks++) {
        qa[ks][0] = fu(Ps[rq0 * 72 + ks * 8 + tig] * 0.125f);
        qa[ks][2] = fu(Ps[rq0 * 72 + ks * 8 + tig + 4] * 0.125f);
        qa[ks][1] = fu(Ps[(rq0 + 8) * 72 + ks * 8 + tig] * 0.125f);
        qa[ks][3] = fu(Ps[(rq0 + 8) * 72 + ks * 8 + tig + 4] * 0.125f);
    }

    const int p0 = (tig < 2) ? 4 * tig     : 4 * tig - 7;   // pos of col 2tig
    const int p1 = (tig < 2) ? 4 * tig + 2 : 4 * tig - 5;   // pos of col 2tig+1

    float m0 = -1e30f, m1 = -1e30f, l0 = 0.f, l1 = 0.f;
    float sc0s = 0.f, sc1s = 0.f;   // saved scales for deferred O-rescale
    float o[8][4];
#pragma unroll
    for (int i = 0; i < 8; i++)
#pragma unroll
        for (int e = 0; e < 4; e++) o[i][e] = 0.f;

    const int nktFull = 34 + 2 * qtp;
    const int nkt = nktFull < 65 ? nktFull : 65;
    for (int kt = 0; kt < nkt; kt++) {
        CP_WAIT(0);
        __syncthreads();          // K(kt),V(kt) ready & visible

        float* Ks = (kt & 1) ? KsB : KsA;

        // ---- S(kt) = Q @ K^T ----
        float s[8][4];
#pragma unroll
        for (int i = 0; i < 8; i++)
#pragma unroll
            for (int e = 0; e < 4; e++) s[i][e] = 0.f;

#pragma unroll
        for (int ks = 0; ks < 8; ks++) {
            const int kcol = ks * 8 + 2 * tig;
#pragma unroll
            for (int nt = 0; nt < 8; nt++) {
                float2 bv = *(const float2*)&Ks[(nt * 8 + gid) * 72 + kcol];
                uint32_t bb[2] = {fu(bv.x), fu(bv.y)};
                mma8(s[nt], qa[ks], bb);
            }
        }

        // ---- deferred PV(kt-1): O = O*sc + P(kt-1) @ V(kt-1) ----
        if (kt > 0) {
            float* Vp = (kt & 1) ? VsA : VsB;   // buffer (kt-1)%2
#pragma unroll
            for (int dt = 0; dt < 8; dt++) {
                o[dt][0] *= sc0s; o[dt][1] *= sc0s;
                o[dt][2] *= sc1s; o[dt][3] *= sc1s;
            }
#pragma unroll
            for (int ks = 0; ks < 8; ks++) {
                const int kcol = ks * 8 + 2 * tig;
                float2 u = *(const float2*)&Ps[rq0 * 72 + kcol];
                float2 w = *(const float2*)&Ps[(rq0 + 8) * 72 + kcol];
                uint32_t a[4] = {fu(u.x), fu(w.x), fu(u.y), fu(w.y)};
#pragma unroll
                for (int dt = 0; dt < 8; dt++) {
                    float2 bv = *(const float2*)&Vp[(dt * 8 + gid) * 72 + kcol];
                    uint32_t bb[2] = {fu(bv.x), fu(bv.y)};
                    mma8(o[dt], a, bb);
                }
            }
        }

        __syncthreads();          // all warps done reading K(kt), V(kt-1), P(kt-1)
        if (kt + 1 < nkt)
            loadKV(kt + 1, (kt & 1) ? KsA : KsB, (kt & 1) ? VsA : VsB);

        // ---- causal mask on last two k-tiles ----
        if (kt >= nkt - 2) {
            const int off = kt * 64 - QSTART - qb;
#pragma unroll
            for (int nt = 0; nt < 8; nt++) {
#pragma unroll
                for (int e = 0; e < 4; e++) {
                    int kc  = nt * 8 + 2 * tig + (e & 1);
                    int rit = warp * 16 + gid + ((e >> 1) << 3);
                    if (kc + off > rit) s[nt][e] = -1e30f;
                }
            }
        }

        // ---- online softmax(kt) -> P(kt), saved scales ----
        float rm0 = -1e30f, rm1 = -1e30f;
#pragma unroll
        for (int nt = 0; nt < 8; nt++) {
            rm0 = fmaxf(rm0, fmaxf(s[nt][0], s[nt][1]));
            rm1 = fmaxf(rm1, fmaxf(s[nt][2], s[nt][3]));
        }
        rm0 = fmaxf(rm0, __shfl_xor_sync(0xffffffffu, rm0, 1));
        rm0 = fmaxf(rm0, __shfl_xor_sync(0xffffffffu, rm0, 2));
        rm1 = fmaxf(rm1, __shfl_xor_sync(0xffffffffu, rm1, 1));
        rm1 = fmaxf(rm1, __shfl_xor_sync(0xffffffffu, rm1, 2));

        float mn0 = fmaxf(m0, rm0), mn1 = fmaxf(m1, rm1);
        sc0s = __expf(m0 - mn0);
        sc1s = __expf(m1 - mn1);
        m0 = mn0; m1 = mn1;

        float rs0 = 0.f, rs1 = 0.f;
#pragma unroll
        for (int nt = 0; nt < 8; nt++) {
            s[nt][0] = __expf(s[nt][0] - m0); rs0 += s[nt][0];
            s[nt][1] = __expf(s[nt][1] - m0); rs0 += s[nt][1];
            s[nt][2] = __expf(s[nt][2] - m1); rs1 += s[nt][2];
            s[nt][3] = __expf(s[nt][3] - m1); rs1 += s[nt][3];
        }
        rs0 += __shfl_xor_sync(0xffffffffu, rs0, 1);
        rs0 += __shfl_xor_sync(0xffffffffu, rs0, 2);
        rs1 += __shfl_xor_sync(0xffffffffu, rs1, 1);
        rs1 += __shfl_xor_sync(0xffffffffu, rs1, 2);
        l0 = l0 * sc0s + rs0;
        l1 = l1 * sc1s + rs1;

        // P(kt) -> Ps at permuted positions (warp-private rows), rounded tf32
#pragma unroll
        for (int nt = 0; nt < 8; nt++) {
            Ps[rq0 * 72 + nt * 8 + p0]       = rnd(s[nt][0]);
            Ps[rq0 * 72 + nt * 8 + p1]       = rnd(s[nt][1]);
            Ps[(rq0 + 8) * 72 + nt * 8 + p0] = rnd(s[nt][2]);
            Ps[(rq0 + 8) * 72 + nt * 8 + p1] = rnd(s[nt][3]);
        }
        __syncwarp();
    }

    // ---- final deferred PV(nkt-1) ----
    {
        float* Vp = ((nkt - 1) & 1) ? VsB : VsA;
#pragma unroll
        for (int dt = 0; dt < 8; dt++) {
            o[dt][0] *= sc0s; o[dt][1] *= sc0s;
            o[dt][2] *= sc1s; o[dt][3] *= sc1s;
        }
#pragma unroll
        for (int ks = 0; ks < 8; ks++) {
            const int kcol = ks * 8 + 2 * tig;
            float2 u = *(const float2*)&Ps[rq0 * 72 + kcol];
            float2 w = *(const float2*)&Ps[(rq0 + 8) * 72 + kcol];
            uint32_t a[4] = {fu(u.x), fu(w.x), fu(u.y), fu(w.y)};
#pragma unroll
            for (int dt = 0; dt < 8; dt++) {
                float2 bv = *(const float2*)&Vp[(dt * 8 + gid) * 72 + kcol];
                uint32_t bb[2] = {fu(bv.x), fu(bv.y)};
                mma8(o[dt], a, bb);
            }
        }
    }

    // Epilogue: write g_AO in k-permuted layout (matches g_Wor for gemm_out)
    const float il0 = 1.f / l0, il1 = 1.f / l1;
    const int qr0 = qb + rq0, qr1 = qb + rq0 + 8;
#pragma unroll
    for (int dt = 0; dt < 8; dt++) {
        int base = h * DH + dt * 8;
        if (qr0 < LQ) {
            g_AO[(size_t)qr0 * DM + base + p0] = rnd(o[dt][0] * il0);
            g_AO[(size_t)qr0 * DM + base + p1] = rnd(o[dt][1] * il0);
        }
        if (qr1 < LQ) {
            g_AO[(size_t)qr1 * DM + base + p0] = rnd(o[dt][2] * il1);
            g_AO[(size_t)qr1 * DM + base + p1] = rnd(o[dt][3] * il1);
        }
    }
}

// ============================================================================
extern "C" void kernel_launch(void* const* d_in, const int* in_sizes, int n_in,
                              void* d_out, int out_size) {
    const float* x     = (const float*)d_in[0];
    const float* W_S   = (const float*)d_in[1];
    const float* W_NS  = (const float*)d_in[2];
    const float* W_out = (const float*)d_in[3];
    float* out = (float*)d_out;
    (void)in_sizes; (void)n_in; (void)out_size;

    const int gemm_smem = 4 * 5120 * (int)sizeof(float);   // 81920
    const int attn_smem = 27648 * (int)sizeof(float);      // 110592

    cudaFuncSetAttribute(fused_qkv,   cudaFuncAttributeMaxDynamicSharedMemorySize, gemm_smem);
    cudaFuncSetAttribute(gemm_out,    cudaFuncAttributeMaxDynamicSharedMemorySize, gemm_smem);
    cudaFuncSetAttribute(attn_kernel, cudaFuncAttributeMaxDynamicSharedMemorySize, attn_smem);

    // 0) prep: round+permute x; transpose+round+permute W_S, W_out; zero d_out
    prep_x<<<512, 256>>>(x);
    prep_tr<<<dim3(3 * DM / 32, DM / 32), 256>>>(W_S, 0);
    prep_tr<<<dim3(DM / 32, DM / 32), 256>>>(W_out, 1);
    zeroC<<<(LQ * DM / 4 + 255) / 256, 256>>>(out);

    // 1+2) fused: live qkv GEMM tiles (640, K permuted in epilogue) + NS (192)
    fused_qkv<<<832, 256, gemm_smem>>>(x, W_NS);

    // 2b) repack V (transpose + token-permute)
    repack_Vt<<<dim3(LK / 32, DM / 32), 256>>>();

    // 3) attention: 17 q-pair tiles x 16 heads, longest first
    attn_kernel<<<17 * NH, 256, attn_smem>>>();

    // 4) output projection, split-K x2, atomic accumulate
    gemm_out<<<dim3(1024 / 128, (LQ + 127) / 128, 2), 256, gemm_smem>>>(out);
}